// round 10
// baseline (speedup 1.0000x reference)
#include <cuda_runtime.h>
#include <cstddef>

// GraphSage gather + cosine top-16 + mean.  (Round 10 = R3 consolidated)
//   d_in[0] nodes  : int32 [N]
//   d_in[1] neigh  : int32 [N, 32]
//   d_in[2] u2e_visual : f32 [500000, 64]
//   d_in[3] u2e_text   : f32 [500000, 64]
// Output: f32 concat(u_v, u_t, v_agg, t_agg), each [N, 64].
//
// Proven-best structure: one warp per (node, modality), modality-major order
// (single-table L2 phase), 8-lane-group sim loop with independent 3-step
// butterflies, rank-count stable top-16, 16-lane mean loop, plain __ldg for
// table rows, evict-first (__ldcs/__stcs) for index/output streams.
// Deltas vs R3 (both individually verified, neither previously benched in
// isolation at high occupancy):
//  * group g owns neighbors 8g..8g+7: sim lands on lane L directly — no
//    redistribute shfl, one fdividef per lane instead of eight.
//  * __launch_bounds__(256, 8): regs=32 exactly fills the 64K register file
//    at 2048 threads/SM -> 100% theoretical occupancy (R3 capped at 53/64).

#define DEG   32
#define TOPK  16
#define EMB   64

__global__ __launch_bounds__(256, 8) void gs_kernel(
    const int*   __restrict__ nodes,
    const int*   __restrict__ neigh,
    const float* __restrict__ uv,
    const float* __restrict__ ut,
    float*       __restrict__ out,
    int n)
{
    const unsigned FULL = 0xffffffffu;
    int wg = (int)((blockIdx.x * blockDim.x + threadIdx.x) >> 5);
    if (wg >= 2 * n) return;
    int lane = threadIdx.x & 31;

    // modality-major task order: [0,n) = visual, [n,2n) = text
    int m    = (wg >= n) ? 1 : 0;
    int node = wg - m * n;
    const float* __restrict__ emb = m ? ut : uv;

    int g = lane >> 3;     // 8-lane group id (0..3): owns neighbors 8g..8g+7
    int s = lane & 7;      // sub-lane within group

    // ---- center gather (lane s holds float4 s and s+8 of the row) ----
    int cidx = __ldcs(nodes + node);
    const float4* crow = (const float4*)(emb + (size_t)cidx * EMB);
    float4 ua = __ldg(crow + s);
    float4 ub = __ldg(crow + s + 8);

    size_t nn = (size_t)n * EMB;
    float4* cout = (float4*)(out + (size_t)m * nn + (size_t)node * EMB);
    if (g == 0) { __stcs(cout + s, ua); __stcs(cout + s + 8, ub); }

    // ---- neighbor indices: lane k holds neigh[node][k] ----
    int nidx = __ldcs(neigh + (size_t)node * DEG + lane);

    // ---- rank value per neighbor: dot*|dot|/||v||^2 (strictly monotone in
    //      cosine; center norm is a positive per-node constant) ----
    float fd = 0.0f, fn = 1.0f;
    #pragma unroll
    for (int t = 0; t < 8; t++) {
        int j = __shfl_sync(FULL, nidx, 8 * g + t);
        const float4* vrow = (const float4*)(emb + (size_t)j * EMB);
        float4 va = __ldg(vrow + s);
        float4 vb = __ldg(vrow + s + 8);
        float dot = va.x * ua.x + va.y * ua.y + va.z * ua.z + va.w * ua.w
                  + vb.x * ub.x + vb.y * ub.y + vb.z * ub.z + vb.w * ub.w;
        float nsq = va.x * va.x + va.y * va.y + va.z * va.z + va.w * va.w
                  + vb.x * vb.x + vb.y * vb.y + vb.z * vb.z + vb.w * vb.w;
        #pragma unroll
        for (int d = 1; d < 8; d <<= 1) {        // independent 3-step butterflies
            dot += __shfl_xor_sync(FULL, dot, d);
            nsq += __shfl_xor_sync(FULL, nsq, d);
        }
        if (s == t) { fd = dot; fn = nsq; }      // lane 8g+t keeps neighbor 8g+t
    }
    float mysim = __fdividef(fd * fabsf(fd), fn + 1e-20f);

    // ---- stable top-16 via rank count (matches jax.lax.top_k tie-break) ----
    int cnt = 0;
    #pragma unroll
    for (int d = 1; d < DEG; d++) {
        float o = __shfl_xor_sync(FULL, mysim, d);
        int jl = lane ^ d;
        cnt += (o > mysim) || (o == mysim && jl < lane);
    }
    unsigned sel = __ballot_sync(FULL, cnt < TOPK);   // exactly TOPK bits set

    // ---- mean of selected (unnormalized) rows; re-reads mostly L1/L2-hit ----
    int half = lane >> 4;   // 16-lane halves: 2 neighbors per iteration
    int sub  = lane & 15;
    float4 acc = make_float4(0.f, 0.f, 0.f, 0.f);
    #pragma unroll
    for (int k = 0; k < DEG; k += 2) {
        int kk = k + half;
        int j = __shfl_sync(FULL, nidx, kk);
        if (sel & (1u << kk)) {
            float4 vv = __ldg((const float4*)(emb + (size_t)j * EMB) + sub);
            acc.x += vv.x; acc.y += vv.y; acc.z += vv.z; acc.w += vv.w;
        }
    }
    acc.x += __shfl_xor_sync(FULL, acc.x, 16);
    acc.y += __shfl_xor_sync(FULL, acc.y, 16);
    acc.z += __shfl_xor_sync(FULL, acc.z, 16);
    acc.w += __shfl_xor_sync(FULL, acc.w, 16);

    if (half == 0) {
        const float sc = 1.0f / (float)TOPK;
        float4 r = make_float4(acc.x * sc, acc.y * sc, acc.z * sc, acc.w * sc);
        float4* aout = (float4*)(out + (size_t)(2 + m) * nn + (size_t)node * EMB);
        __stcs(aout + sub, r);
    }
}

extern "C" void kernel_launch(void* const* d_in, const int* in_sizes, int n_in,
                              void* d_out, int out_size) {
    const int*   nodes = (const int*)d_in[0];
    const int*   neigh = (const int*)d_in[1];
    const float* uv    = (const float*)d_in[2];
    const float* ut    = (const float*)d_in[3];
    float*       out   = (float*)d_out;
    int n = in_sizes[0];
    int warps = 2 * n;
    int threads = 256;
    int blocks = (warps * 32 + threads - 1) / threads;
    gs_kernel<<<blocks, threads>>>(nodes, neigh, uv, ut, out, n);
}

// round 11
// speedup vs baseline: 1.2641x; 1.2641x over previous
#include <cuda_runtime.h>
#include <cstddef>

// GraphSage gather + cosine top-16 + mean.  (Round 11 = exact R3 + compacted mean)
//   d_in[0] nodes  : int32 [N]
//   d_in[1] neigh  : int32 [N, 32]
//   d_in[2] u2e_visual : f32 [500000, 64]
//   d_in[3] u2e_text   : f32 [500000, 64]
// Output: f32 concat(u_v, u_t, v_agg, t_agg), each [N, 64].
//
// Base is the verified 121us R3 kernel: one warp per (node, modality),
// modality-major order, 8-lane-group sim loop with IN-LOOP fdividef +
// predicated keep + redistribute (this interleaved form pins ptxas's load
// schedule at MLP_p1~3; every front-batched variant regressed via cross-CTA
// L1tex queue contention), gather-form rank count, (256,7) occupancy.
// Single delta: the mean loop first compacts the 16 selected neighbor
// indices into lanes 0..15 (__fns), then runs 8 unconditional iterations
// (2 rows/iter) instead of 16 predicated ones. Same 16 loads, ~55 fewer
// instructions per warp.

#define DEG   32
#define TOPK  16
#define EMB   64

__global__ __launch_bounds__(256, 7) void gs_kernel(
    const int*   __restrict__ nodes,
    const int*   __restrict__ neigh,
    const float* __restrict__ uv,
    const float* __restrict__ ut,
    float*       __restrict__ out,
    int n)
{
    const unsigned FULL = 0xffffffffu;
    int wg = (int)((blockIdx.x * blockDim.x + threadIdx.x) >> 5);
    if (wg >= 2 * n) return;
    int lane = threadIdx.x & 31;

    // modality-major task order: [0,n) = visual, [n,2n) = text
    int m    = (wg >= n) ? 1 : 0;
    int node = wg - m * n;
    const float* __restrict__ emb = m ? ut : uv;

    int g = lane >> 3;     // 8-lane group id (0..3) — one neighbor per group
    int s = lane & 7;      // sub-lane within group — 8 floats per lane

    // ---- center gather (lane s holds float4 s and s+8 of the row) ----
    int cidx = __ldcs(nodes + node);
    const float4* crow = (const float4*)(emb + (size_t)cidx * EMB);
    float4 ua = __ldg(crow + s);
    float4 ub = __ldg(crow + s + 8);

    size_t nn = (size_t)n * EMB;
    float4* cout = (float4*)(out + (size_t)m * nn + (size_t)node * EMB);
    if (g == 0) { __stcs(cout + s, ua); __stcs(cout + s + 8, ub); }

    // ---- neighbor indices: lane k holds neigh[node][k] ----
    int nidx = __ldcs(neigh + (size_t)node * DEG + lane);

    // ---- ranking value: dot*|dot|/||v||^2  (strictly monotone in cosine;
    //      center norm is a positive per-node constant, irrelevant) ----
    float tmp = 0.0f;
    #pragma unroll
    for (int it = 0; it < 8; it++) {
        int j = __shfl_sync(FULL, nidx, 4 * it + g);
        const float4* vrow = (const float4*)(emb + (size_t)j * EMB);
        float4 va = __ldg(vrow + s);
        float4 vb = __ldg(vrow + s + 8);
        float dot = va.x * ua.x + va.y * ua.y + va.z * ua.z + va.w * ua.w
                  + vb.x * ub.x + vb.y * ub.y + vb.z * ub.z + vb.w * ub.w;
        float nsq = va.x * va.x + va.y * va.y + va.z * va.z + va.w * va.w
                  + vb.x * vb.x + vb.y * vb.y + vb.z * vb.z + vb.w * vb.w;
        #pragma unroll
        for (int d = 1; d < 8; d <<= 1) {        // 3-step butterfly per group
            dot += __shfl_xor_sync(FULL, dot, d);
            nsq += __shfl_xor_sync(FULL, nsq, d);
        }
        float r = __fdividef(dot * fabsf(dot), nsq + 1e-20f);
        if (s == it) tmp = r;                    // lane L holds r(4*(L&7)+(L>>3))
    }
    // redistribute so lane j holds r(j): src(j) = ((j&3)<<3) | (j>>2)
    float mysim = __shfl_sync(FULL, tmp, ((lane & 3) << 3) | (lane >> 2));

    // ---- stable top-16 via rank count (matches jax.lax.top_k tie-break) ----
    int cnt = 0;
    #pragma unroll
    for (int jl = 0; jl < DEG; jl++) {
        float o = __shfl_sync(FULL, mysim, jl);
        cnt += (o > mysim) || (o == mysim && jl < lane);
    }
    unsigned sel = __ballot_sync(FULL, cnt < TOPK);   // exactly TOPK bits set

    // ---- compact the 16 selected indices into lanes 0..15 ----
    // lane p (p<16) -> table index of the p-th selected neighbor (ascending
    // neighbor order; sum order only affects fp associativity).
    int pos  = __fns(sel, 0, 1 + lane);               // lane>=16: unused
    int jsel = __shfl_sync(FULL, nidx, pos & 31);

    // ---- mean: 8 unconditional iterations, 2 selected rows each ----
    int half = lane >> 4;   // which of the pair this half-warp handles
    int sub  = lane & 15;   // float4 slot within the 64-float row
    float4 acc = make_float4(0.f, 0.f, 0.f, 0.f);
    #pragma unroll
    for (int i = 0; i < 8; i++) {
        int j = __shfl_sync(FULL, jsel, 2 * i + half);
        float4 v = __ldg((const float4*)(emb + (size_t)j * EMB) + sub);
        acc.x += v.x; acc.y += v.y; acc.z += v.z; acc.w += v.w;
    }
    acc.x += __shfl_xor_sync(FULL, acc.x, 16);
    acc.y += __shfl_xor_sync(FULL, acc.y, 16);
    acc.z += __shfl_xor_sync(FULL, acc.z, 16);
    acc.w += __shfl_xor_sync(FULL, acc.w, 16);

    if (half == 0) {
        const float sc = 1.0f / (float)TOPK;
        float4 r = make_float4(acc.x * sc, acc.y * sc, acc.z * sc, acc.w * sc);
        float4* aout = (float4*)(out + (size_t)(2 + m) * nn + (size_t)node * EMB);
        __stcs(aout + sub, r);
    }
}

extern "C" void kernel_launch(void* const* d_in, const int* in_sizes, int n_in,
                              void* d_out, int out_size) {
    const int*   nodes = (const int*)d_in[0];
    const int*   neigh = (const int*)d_in[1];
    const float* uv    = (const float*)d_in[2];
    const float* ut    = (const float*)d_in[3];
    float*       out   = (float*)d_out;
    int n = in_sizes[0];
    int warps = 2 * n;
    int threads = 256;
    int blocks = (warps * 32 + threads - 1) / threads;
    gs_kernel<<<blocks, threads>>>(nodes, neigh, uv, ut, out, n);
}

// round 12
// speedup vs baseline: 1.3614x; 1.0770x over previous
#include <cuda_runtime.h>
#include <cstddef>

// GraphSage gather + cosine top-16 + mean.  (Round 12 = R11 + hoisted divide)
//   d_in[0] nodes  : int32 [N]
//   d_in[1] neigh  : int32 [N, 32]
//   d_in[2] u2e_visual : f32 [500000, 64]
//   d_in[3] u2e_text   : f32 [500000, 64]
// Output: f32 concat(u_v, u_t, v_agg, t_agg), each [N, 64].
//
// Base = verified 117.3us R11: one warp per (node, modality), modality-major
// order, 8-lane-group sim loop with IN-LOOP predicated keep (pins ptxas's
// load schedule; every front-batched variant regressed via cross-CTA L1tex
// queue contention), rank-count top-16, __fns-compacted unconditional mean.
// Single delta: the sim loop keeps the raw (dot, nsq) pair instead of the
// divided rank value; both are redistributed (2 shfls) and ONE
// fabs*mul*fdividef chain runs per lane instead of eight (~45 fewer
// instructions/warp on the fma/MUFU pipes). Per-neighbor arithmetic is
// identical -> same selection, same rel_err.

#define DEG   32
#define TOPK  16
#define EMB   64

__global__ __launch_bounds__(256, 7) void gs_kernel(
    const int*   __restrict__ nodes,
    const int*   __restrict__ neigh,
    const float* __restrict__ uv,
    const float* __restrict__ ut,
    float*       __restrict__ out,
    int n)
{
    const unsigned FULL = 0xffffffffu;
    int wg = (int)((blockIdx.x * blockDim.x + threadIdx.x) >> 5);
    if (wg >= 2 * n) return;
    int lane = threadIdx.x & 31;

    // modality-major task order: [0,n) = visual, [n,2n) = text
    int m    = (wg >= n) ? 1 : 0;
    int node = wg - m * n;
    const float* __restrict__ emb = m ? ut : uv;

    int g = lane >> 3;     // 8-lane group id (0..3) — one neighbor per group
    int s = lane & 7;      // sub-lane within group — 8 floats per lane

    // ---- center gather (lane s holds float4 s and s+8 of the row) ----
    int cidx = __ldcs(nodes + node);
    const float4* crow = (const float4*)(emb + (size_t)cidx * EMB);
    float4 ua = __ldg(crow + s);
    float4 ub = __ldg(crow + s + 8);

    size_t nn = (size_t)n * EMB;
    float4* cout = (float4*)(out + (size_t)m * nn + (size_t)node * EMB);
    if (g == 0) { __stcs(cout + s, ua); __stcs(cout + s + 8, ub); }

    // ---- neighbor indices: lane k holds neigh[node][k] ----
    int nidx = __ldcs(neigh + (size_t)node * DEG + lane);

    // ---- per-neighbor (dot, nsq); in-loop predicated keep (schedule pin) ----
    float fd = 0.0f, fn = 1.0f;
    #pragma unroll
    for (int it = 0; it < 8; it++) {
        int j = __shfl_sync(FULL, nidx, 4 * it + g);
        const float4* vrow = (const float4*)(emb + (size_t)j * EMB);
        float4 va = __ldg(vrow + s);
        float4 vb = __ldg(vrow + s + 8);
        float dot = va.x * ua.x + va.y * ua.y + va.z * ua.z + va.w * ua.w
                  + vb.x * ub.x + vb.y * ub.y + vb.z * ub.z + vb.w * ub.w;
        float nsq = va.x * va.x + va.y * va.y + va.z * va.z + va.w * va.w
                  + vb.x * vb.x + vb.y * vb.y + vb.z * vb.z + vb.w * vb.w;
        #pragma unroll
        for (int d = 1; d < 8; d <<= 1) {        // 3-step butterfly per group
            dot += __shfl_xor_sync(FULL, dot, d);
            nsq += __shfl_xor_sync(FULL, nsq, d);
        }
        if (s == it) { fd = dot; fn = nsq; }     // lane L keeps nbr 4*(L&7)+(L>>3)
    }
    // redistribute so lane j holds neighbor j's pair: src(j) = ((j&3)<<3)|(j>>2)
    int src = ((lane & 3) << 3) | (lane >> 2);
    float rd = __shfl_sync(FULL, fd, src);
    float rn = __shfl_sync(FULL, fn, src);
    // ranking value: dot*|dot|/||v||^2 — strictly monotone in cosine
    // (center norm is a positive per-node constant, irrelevant to order).
    float mysim = __fdividef(rd * fabsf(rd), rn + 1e-20f);

    // ---- stable top-16 via rank count (matches jax.lax.top_k tie-break) ----
    int cnt = 0;
    #pragma unroll
    for (int jl = 0; jl < DEG; jl++) {
        float o = __shfl_sync(FULL, mysim, jl);
        cnt += (o > mysim) || (o == mysim && jl < lane);
    }
    unsigned sel = __ballot_sync(FULL, cnt < TOPK);   // exactly TOPK bits set

    // ---- compact the 16 selected indices into lanes 0..15 ----
    int pos  = __fns(sel, 0, 1 + lane);               // lane>=16: unused
    int jsel = __shfl_sync(FULL, nidx, pos & 31);

    // ---- mean: 8 unconditional iterations, 2 selected rows each ----
    int half = lane >> 4;   // which of the pair this half-warp handles
    int sub  = lane & 15;   // float4 slot within the 64-float row
    float4 acc = make_float4(0.f, 0.f, 0.f, 0.f);
    #pragma unroll
    for (int i = 0; i < 8; i++) {
        int j = __shfl_sync(FULL, jsel, 2 * i + half);
        float4 v = __ldg((const float4*)(emb + (size_t)j * EMB) + sub);
        acc.x += v.x; acc.y += v.y; acc.z += v.z; acc.w += v.w;
    }
    acc.x += __shfl_xor_sync(FULL, acc.x, 16);
    acc.y += __shfl_xor_sync(FULL, acc.y, 16);
    acc.z += __shfl_xor_sync(FULL, acc.z, 16);
    acc.w += __shfl_xor_sync(FULL, acc.w, 16);

    if (half == 0) {
        const float sc = 1.0f / (float)TOPK;
        float4 r = make_float4(acc.x * sc, acc.y * sc, acc.z * sc, acc.w * sc);
        float4* aout = (float4*)(out + (size_t)(2 + m) * nn + (size_t)node * EMB);
        __stcs(aout + sub, r);
    }
}

extern "C" void kernel_launch(void* const* d_in, const int* in_sizes, int n_in,
                              void* d_out, int out_size) {
    const int*   nodes = (const int*)d_in[0];
    const int*   neigh = (const int*)d_in[1];
    const float* uv    = (const float*)d_in[2];
    const float* ut    = (const float*)d_in[3];
    float*       out   = (float*)d_out;
    int n = in_sizes[0];
    int warps = 2 * n;
    int threads = 256;
    int blocks = (warps * 32 + threads - 1) / threads;
    gs_kernel<<<blocks, threads>>>(nodes, neigh, uv, ut, out, n);
}